// round 1
// baseline (speedup 1.0000x reference)
#include <cuda_runtime.h>
#include <math.h>

// Problem constants
#define NROWS   131072            // 16 * 8192
#define DIM     64
#define KCODES  1024
#define NLEVELS 4

// Output layout (float32): [quantized_out | codes (level-major, as float) | total_loss]
#define CODES_OFF 8388608         // NROWS * DIM
#define LOSS_OFF  8912896         // CODES_OFF + NLEVELS * NROWS

// Tiling
#define MB 64                     // rows per CTA
#define NC 128                    // codes per smem chunk
#define TM 4                      // rows per thread
#define TN 8                      // codes per thread (per chunk)
// 256 threads: tx = tid & 15 (code dir), ty = tid >> 4 (row dir)
// thread's rows:  i*16 + ty   (i in 0..3)
// thread's codes: ch*NC + j*16 + tx  (j in 0..7)

__device__ __align__(16) float g_residual[NROWS * DIM];
__device__ float g_cnorm[KCODES];
__device__ float g_counts[KCODES];
__device__ float g_sqerr;
__device__ float g_loss;

// Per-level prep: ||c||^2, zero counts/sqerr (and loss at level 0)
__global__ void prep_kernel(const float* __restrict__ cb, int level) {
    int c = blockIdx.x * blockDim.x + threadIdx.x;
    if (c < KCODES) {
        const float4* v = (const float4*)cb;
        float s = 0.f;
        #pragma unroll
        for (int t = 0; t < DIM / 4; t++) {
            float4 f = v[c * (DIM / 4) + t];
            s += f.x * f.x + f.y * f.y + f.z * f.z + f.w * f.w;
        }
        g_cnorm[c]  = s;
        g_counts[c] = 0.f;
    }
    if (blockIdx.x == 0 && threadIdx.x == 0) {
        g_sqerr = 0.f;
        if (level == 0) g_loss = 0.f;
    }
}

// Main fused kernel: argmin GEMM + residual update + sq-error + histogram + codes
__global__ __launch_bounds__(256) void rvq_main_kernel(
    const float* __restrict__ x0,        // original x
    const float* __restrict__ cb,        // this level's codebook [K][D]
    float* __restrict__ qout,            // d_out + 0 (written only at last level)
    float* __restrict__ codes_out,       // d_out + CODES_OFF + level*NROWS
    int level)
{
    extern __shared__ float sm[];
    float* As   = sm;                              // [MB][65]
    float* Bs   = sm + MB * 65;                    // [NC][65]
    int*   sBest = (int*)(sm + MB * 65 + NC * 65); // [MB]
    float* sRed  = (float*)(sBest + MB);           // [8]

    const int tid = threadIdx.x;
    const int tx  = tid & 15;
    const int ty  = tid >> 4;
    const size_t rowBase = (size_t)blockIdx.x * MB;

    const float* xin = (level == 0) ? x0 : g_residual;

    // Load A tile (MB rows x DIM) into smem, stride 65 (bank-safe)
    {
        const float4* src = (const float4*)(xin + rowBase * DIM);
        #pragma unroll
        for (int it = 0; it < 4; it++) {
            int v = tid + it * 256;        // 0..1023 float4 index
            int r = v >> 4, c = v & 15;
            float4 f = src[v];
            float* d = &As[r * 65 + c * 4];
            d[0] = f.x; d[1] = f.y; d[2] = f.z; d[3] = f.w;
        }
    }

    float best[TM];
    int   bidx[TM];
    #pragma unroll
    for (int i = 0; i < TM; i++) { best[i] = 3.4028235e38f; bidx[i] = 0; }

    for (int ch = 0; ch < KCODES / NC; ch++) {
        __syncthreads();   // A-load done / previous chunk fully consumed
        // Load B chunk (NC codes x DIM), stride 65
        {
            const float4* bsrc = (const float4*)(cb + (size_t)ch * NC * DIM);
            #pragma unroll
            for (int it = 0; it < 8; it++) {
                int v = tid + it * 256;    // 0..2047 float4 index
                int c = v >> 4, d4 = v & 15;
                float4 f = bsrc[v];
                float* d = &Bs[c * 65 + d4 * 4];
                d[0] = f.x; d[1] = f.y; d[2] = f.z; d[3] = f.w;
            }
        }
        __syncthreads();

        float acc[TM][TN];
        #pragma unroll
        for (int i = 0; i < TM; i++)
            #pragma unroll
            for (int j = 0; j < TN; j++) acc[i][j] = 0.f;

        #pragma unroll 4
        for (int k = 0; k < DIM; k++) {
            float a[TM], b[TN];
            #pragma unroll
            for (int i = 0; i < TM; i++) a[i] = As[(i * 16 + ty) * 65 + k];
            #pragma unroll
            for (int j = 0; j < TN; j++) b[j] = Bs[(j * 16 + tx) * 65 + k];
            #pragma unroll
            for (int i = 0; i < TM; i++)
                #pragma unroll
                for (int j = 0; j < TN; j++)
                    acc[i][j] = fmaf(a[i], b[j], acc[i][j]);
        }

        // Fold into running argmin: score = ||c||^2 - 2*dot (same ordering as full dist)
        #pragma unroll
        for (int j = 0; j < TN; j++) {
            int code = ch * NC + j * 16 + tx;
            float cn = g_cnorm[code];
            #pragma unroll
            for (int i = 0; i < TM; i++) {
                float v = fmaf(-2.f, acc[i][j], cn);
                if (v < best[i] || (v == best[i] && code < bidx[i])) {
                    best[i] = v; bidx[i] = code;
                }
            }
        }
    }

    // Reduce argmin across the 16 tx-threads that share each row (lanes 0..15 / 16..31)
    #pragma unroll
    for (int i = 0; i < TM; i++) {
        float v = best[i]; int ix = bidx[i];
        #pragma unroll
        for (int off = 8; off >= 1; off >>= 1) {
            float v2 = __shfl_down_sync(0xffffffffu, v, off);
            int   i2 = __shfl_down_sync(0xffffffffu, ix, off);
            if (v2 < v || (v2 == v && i2 < ix)) { v = v2; ix = i2; }
        }
        if (tx == 0) {
            int r = i * 16 + ty;
            sBest[r] = ix;
            codes_out[rowBase + r] = (float)ix;
            atomicAdd(&g_counts[ix], 1.0f);
        }
    }
    __syncthreads();

    // Epilogue: residual update + squared-error, coalesced float4; A still in smem
    float sq = 0.f;
    const float4* cb4  = (const float4*)cb;
    float4* res4       = (float4*)(g_residual + rowBase * DIM);
    const float4* x04  = (const float4*)(x0 + rowBase * DIM);
    float4* q4         = (float4*)(qout + rowBase * DIM);
    #pragma unroll
    for (int it = 0; it < 4; it++) {
        int v = tid + it * 256;
        int r = v >> 4, c = v & 15;
        int code = sBest[r];
        float4 q = cb4[code * (DIM / 4) + c];
        float* ap = &As[r * 65 + c * 4];
        float4 rn;
        rn.x = ap[0] - q.x; rn.y = ap[1] - q.y;
        rn.z = ap[2] - q.z; rn.w = ap[3] - q.w;
        sq += rn.x * rn.x + rn.y * rn.y + rn.z * rn.z + rn.w * rn.w;
        res4[v] = rn;
        if (level == NLEVELS - 1) {
            // quantized_out = x - residual_final
            float4 x = x04[v];
            float4 o;
            o.x = x.x - rn.x; o.y = x.y - rn.y;
            o.z = x.z - rn.z; o.w = x.w - rn.w;
            q4[v] = o;
        }
    }
    // Block-reduce sq, one atomic per CTA
    #pragma unroll
    for (int off = 16; off >= 1; off >>= 1)
        sq += __shfl_down_sync(0xffffffffu, sq, off);
    if ((tid & 31) == 0) sRed[tid >> 5] = sq;
    __syncthreads();
    if (tid == 0) {
        float s = 0.f;
        #pragma unroll
        for (int w = 0; w < 8; w++) s += sRed[w];
        atomicAdd(&g_sqerr, s);
    }
}

// Per-level loss finalize: entropy of usage histogram + (rec + commit) term
__global__ void finalize_kernel(float* __restrict__ loss_out, int level) {
    __shared__ float red[8];
    float ent = 0.f;
    for (int c = threadIdx.x; c < KCODES; c += 256) {
        float p = g_counts[c] * (1.0f / (float)NROWS);
        ent -= p * logf(p + 1e-10f);
    }
    #pragma unroll
    for (int off = 16; off >= 1; off >>= 1)
        ent += __shfl_down_sync(0xffffffffu, ent, off);
    if ((threadIdx.x & 31) == 0) red[threadIdx.x >> 5] = ent;
    __syncthreads();
    if (threadIdx.x == 0) {
        float e = 0.f;
        #pragma unroll
        for (int w = 0; w < 8; w++) e += red[w];
        // rec_loss + com_loss = (1 + 0.25) * mean((r - q)^2)
        g_loss += 1.25f * g_sqerr * (1.0f / (float)(NROWS * DIM)) + 0.1f * e;
        if (level == NLEVELS - 1) loss_out[0] = g_loss;
    }
}

extern "C" void kernel_launch(void* const* d_in, const int* in_sizes, int n_in,
                              void* d_out, int out_size) {
    const float* a0 = (const float*)d_in[0];
    const float* a1 = (const float*)d_in[1];
    const float* x;
    const float* cbs;
    // x has 16*8192*64 = 8388608 elems, codebooks have 4*1024*64 = 262144 elems
    if (in_sizes[0] == NLEVELS * KCODES * DIM) { cbs = a0; x = a1; }
    else                                        { x = a0; cbs = a1; }

    float* out = (float*)d_out;

    size_t smemBytes = (size_t)(MB * 65 + NC * 65) * sizeof(float)
                     + MB * sizeof(int) + 8 * sizeof(float);
    cudaFuncSetAttribute(rvq_main_kernel,
                         cudaFuncAttributeMaxDynamicSharedMemorySize,
                         (int)smemBytes);

    for (int l = 0; l < NLEVELS; l++) {
        const float* cb = cbs + (size_t)l * KCODES * DIM;
        prep_kernel<<<(KCODES + 255) / 256, 256>>>(cb, l);
        rvq_main_kernel<<<NROWS / MB, 256, smemBytes>>>(
            x, cb, out, out + CODES_OFF + (size_t)l * NROWS, l);
        finalize_kernel<<<1, 256>>>(out + LOSS_OFF, l);
    }
}